// round 7
// baseline (speedup 1.0000x reference)
#include <cuda_runtime.h>
#include <cstdint>

#define EPS_F   1e-9f
#define DIM     128
#define NTHR    512
#define CLUSTER 8
#define NBLK    128                  // 16 clusters x 8 CTAs, 1 CTA/SM (200KB smem)
#define SHARD   25000                // ceil(200000 / 8) nodes per CTA shard
#define SMEM_BYTES (SHARD * 8)       // 200,000 B dynamic smem

// Scratch (no allocations allowed)
__device__ double       g_part_prox[NBLK];
__device__ double       g_part_comp[NBLK];
__device__ unsigned int g_done = 0;

// ---------------------------------------------------------------------------
__device__ __forceinline__ uint32_t smem_u32(const void* p) {
    uint32_t a;
    asm("{ .reg .u64 t; cvta.to.shared.u64 t, %1; cvt.u32.u64 %0, t; }"
        : "=r"(a) : "l"(p));
    return a;
}

__device__ __forceinline__ uint32_t ctarank() {
    uint32_t r;
    asm("mov.u32 %0, %%cluster_ctarank;" : "=r"(r));
    return r;
}

// Gather node idx from the cluster-sharded table. Owner CTA = idx & 7,
// byte offset inside owner's shard = (idx>>3)*8 = idx & ~7.
__device__ __forceinline__ float2 dsmem_gather(uint32_t shard_base, int idx) {
    uint32_t laddr = shard_base + ((uint32_t)idx & 0xFFFFFFF8u);
    uint32_t rank  = (uint32_t)idx & 7u;
    uint32_t raddr;
    asm("mapa.shared::cluster.u32 %0, %1, %2;" : "=r"(raddr) : "r"(laddr), "r"(rank));
    uint64_t v;
    asm volatile("ld.shared::cluster.b64 %0, [%1];" : "=l"(v) : "r"(raddr));
    float2 f;
    f.x = __uint_as_float((uint32_t)v);
    f.y = __uint_as_float((uint32_t)(v >> 32));
    return f;
}

__device__ __forceinline__ double block_reduce_double(double v, double* s) {
    int lane = threadIdx.x & 31;
    int wid  = threadIdx.x >> 5;
    #pragma unroll
    for (int o = 16; o; o >>= 1) v += __shfl_down_sync(0xffffffffu, v, o);
    if (lane == 0) s[wid] = v;
    __syncthreads();
    v = (threadIdx.x < (NTHR >> 5)) ? s[threadIdx.x] : 0.0;
    if (wid == 0) {
        #pragma unroll
        for (int o = 16; o; o >>= 1) v += __shfl_down_sync(0xffffffffu, v, o);
    }
    return v;  // valid on thread 0
}

// Exact fp32 rounding-order replication of the reference (no FMA contraction).
__device__ __forceinline__ float ref_inner(float ax, float ay, float bx, float by) {
    float u = __fadd_rn(__fmul_rn(ax, bx), __fmul_rn(ay, by));
    return __fadd_rn(-u, 1.0f);
}

__device__ __forceinline__ float ref_safe_div(float num, float den) {
    float sgn  = (den > 0.0f) ? 1.0f : ((den < 0.0f) ? -1.0f : 0.0f);
    float safe = __fmul_rn(fmaxf(fabsf(den), EPS_F), sgn);
    return __fdiv_rn(num, safe);
}

__device__ __forceinline__ float edge_quad(float2 a, float2 b) {
    float aa  = ref_inner(a.x, a.y, a.x, a.y);
    float bb  = ref_inner(b.x, b.y, b.x, b.y);
    float ab  = ref_inner(a.x, a.y, b.x, b.y);
    float den = __fmul_rn(aa, bb);
    float num = __fsub_rn(__fmul_rn(ab, ab), den);
    return ref_safe_div(num, den);
}

// ---------------------------------------------------------------------------
__global__ __cluster_dims__(CLUSTER, 1, 1) __launch_bounds__(NTHR, 1)
void fused_kernel(const float* __restrict__ z,
                  const int*  __restrict__ src,
                  const int*  __restrict__ dst,
                  long long n_edges, int n_nodes,
                  float* __restrict__ out) {
    extern __shared__ char smem_raw[];
    float2* shard = reinterpret_cast<float2*>(smem_raw);
    __shared__ double s_red[32];
    __shared__ double s_pc[2];
    __shared__ unsigned int s_last;

    uint32_t rank       = ctarank();
    uint32_t shard_base = smem_u32(shard);
    bool     do_comp    = (blockIdx.x < CLUSTER);   // cluster 0 owns compactness

    // ---- phase 1: fill this CTA's shard (nodes with idx&7 == rank) -------
    double comp = 0.0;
    for (int local = threadIdx.x; local < SHARD; local += NTHR) {
        int idx = (local << 3) | (int)rank;
        float2 xy = make_float2(0.0f, 0.0f);
        if (idx < n_nodes) {
            xy = *reinterpret_cast<const float2*>(z + (size_t)idx * DIM);
            if (do_comp) {
                float aa  = ref_inner(xy.x, xy.y, xy.x, xy.y);
                float num = __fsub_rn(1.0f, aa);   // ab*ab - aa*bb, ab=bb=1
                comp += (double)ref_safe_div(num, aa);
            }
        }
        shard[local] = xy;
    }
    double bc = block_reduce_double(comp, s_red);
    if (threadIdx.x == 0) g_part_comp[blockIdx.x] = bc;

    // all shards in this cluster ready before any DSMEM gathers
    asm volatile("barrier.cluster.arrive.aligned;" ::: "memory");
    asm volatile("barrier.cluster.wait.aligned;" ::: "memory");

    // ---- phase 2: proximity over all edges via DSMEM gathers --------------
    long long tid    = (long long)blockIdx.x * NTHR + threadIdx.x;
    long long stride = (long long)NBLK * NTHR;

    double prox = 0.0;
    long long n4 = n_edges >> 2;
    const int4* s4 = reinterpret_cast<const int4*>(src);
    const int4* d4 = reinterpret_cast<const int4*>(dst);
    #pragma unroll 1
    for (long long i = tid; i < n4; i += stride) {
        int4 s = __ldcs(s4 + i);
        int4 d = __ldcs(d4 + i);
        float2 a0 = dsmem_gather(shard_base, s.x), b0 = dsmem_gather(shard_base, d.x);
        float2 a1 = dsmem_gather(shard_base, s.y), b1 = dsmem_gather(shard_base, d.y);
        float2 a2 = dsmem_gather(shard_base, s.z), b2 = dsmem_gather(shard_base, d.z);
        float2 a3 = dsmem_gather(shard_base, s.w), b3 = dsmem_gather(shard_base, d.w);
        float q0 = edge_quad(a0, b0);
        float q1 = edge_quad(a1, b1);
        float q2 = edge_quad(a2, b2);
        float q3 = edge_quad(a3, b3);
        prox += (double)__fadd_rn(__fadd_rn(q0, q1), __fadd_rn(q2, q3));
    }
    for (long long e = (n4 << 2) + tid; e < n_edges; e += stride) {
        float2 a = dsmem_gather(shard_base, src[e]);
        float2 b = dsmem_gather(shard_base, dst[e]);
        prox += (double)edge_quad(a, b);
    }

    double bp = block_reduce_double(prox, s_red);
    if (threadIdx.x == 0) {
        g_part_prox[blockIdx.x] = bp;
        __threadfence();
        unsigned int t = atomicAdd(&g_done, 1u);
        s_last = (t == NBLK - 1) ? 1u : 0u;
    }
    __syncthreads();

    // ---- phase 3: last CTA chip-wide finishes -----------------------------
    if (s_last) {
        double p = 0.0, c = 0.0;
        for (int i = threadIdx.x; i < NBLK; i += NTHR) {
            p += g_part_prox[i];
            c += g_part_comp[i];
        }
        p = block_reduce_double(p, s_red);
        __syncthreads();
        c = block_reduce_double(c, s_red);
        if (threadIdx.x == 0) { s_pc[0] = p; s_pc[1] = c; }
        __syncthreads();

        if (threadIdx.x < 32) {
            int n_sp = (int)((n_edges < 10) ? n_edges : 10);
            double q = 0.0;
            if (threadIdx.x < n_sp) {
                int si = src[threadIdx.x], di = dst[threadIdx.x];
                float2 a = *reinterpret_cast<const float2*>(z + (size_t)si * DIM);
                float2 b = *reinterpret_cast<const float2*>(z + (size_t)di * DIM);
                // lines: cross([x,y,1],[0,0,1]) = (y, -x, 0); time = 0
                float aa  = -__fadd_rn(__fmul_rn(a.y, a.y), __fmul_rn(a.x, a.x));
                float bb  = -__fadd_rn(__fmul_rn(b.y, b.y), __fmul_rn(b.x, b.x));
                float ab  = -__fadd_rn(__fmul_rn(a.y, b.y), __fmul_rn(a.x, b.x));
                float den = __fmul_rn(aa, bb);
                float num = __fsub_rn(__fmul_rn(ab, ab), den);
                q = (double)ref_safe_div(num, den);
            }
            #pragma unroll
            for (int o = 16; o; o >>= 1) q += __shfl_down_sync(0xffffffffu, q, o);
            if (threadIdx.x == 0) {
                double prox_m = s_pc[0] / (double)n_edges;
                double comp_m = s_pc[1] / (double)n_nodes;
                double spr_m  = q / (double)n_sp;
                out[0] = (float)((prox_m + comp_m) + 0.1 * spr_m);
                g_done = 0u;   // reset for next graph replay
            }
        }
    }

    // no CTA may exit while same-cluster peers might still read its shard
    asm volatile("barrier.cluster.arrive.aligned;" ::: "memory");
    asm volatile("barrier.cluster.wait.aligned;" ::: "memory");
}

// ---------------------------------------------------------------------------
extern "C" void kernel_launch(void* const* d_in, const int* in_sizes, int n_in,
                              void* d_out, int out_size) {
    const float* z  = (const float*)d_in[0];
    const int*   ei = (const int*)d_in[1];

    int       n_nodes = in_sizes[0] / DIM;
    long long n_edges = (long long)in_sizes[1] / 2;
    const int* src = ei;
    const int* dst = ei + n_edges;

    cudaFuncSetAttribute(fused_kernel,
                         cudaFuncAttributeMaxDynamicSharedMemorySize, SMEM_BYTES);

    fused_kernel<<<NBLK, NTHR, SMEM_BYTES>>>(z, src, dst, n_edges, n_nodes,
                                             (float*)d_out);
}

// round 8
// speedup vs baseline: 5.3723x; 5.3723x over previous
#include <cuda_runtime.h>
#include <cstdint>

#define EPS_F 1e-9f
#define DIM   128
#define NTHR  256
#define EBLK  1184
#define NBA_MAX 1024
#define MAX_NODES 200000

// Scratch (no allocations allowed)
__device__ float2       g_tab[MAX_NODES];
__device__ double       g_part_prox[EBLK];
__device__ double       g_part_comp[NBA_MAX];
__device__ unsigned int g_done = 0;

// ---------------------------------------------------------------------------
// L2-cached gather (no L1 line allocation -> no fill wavefronts)
__device__ __forceinline__ float2 ldcg_f2(const float2* p) {
    float2 r;
    asm volatile("ld.global.cg.v2.f32 {%0, %1}, [%2];"
                 : "=f"(r.x), "=f"(r.y) : "l"(p));
    return r;
}

__device__ __forceinline__ double block_reduce_double(double v, double* s) {
    int lane = threadIdx.x & 31;
    int wid  = threadIdx.x >> 5;
    #pragma unroll
    for (int o = 16; o; o >>= 1) v += __shfl_down_sync(0xffffffffu, v, o);
    if (lane == 0) s[wid] = v;
    __syncthreads();
    v = (threadIdx.x < (NTHR >> 5)) ? s[threadIdx.x] : 0.0;
    if (wid == 0) {
        #pragma unroll
        for (int o = 16; o; o >>= 1) v += __shfl_down_sync(0xffffffffu, v, o);
    }
    return v;  // valid on thread 0
}

// Exact fp32 rounding-order replication of the reference (no FMA contraction).
__device__ __forceinline__ float ref_inner(float ax, float ay, float bx, float by) {
    float u = __fadd_rn(__fmul_rn(ax, bx), __fmul_rn(ay, by));
    return __fadd_rn(-u, 1.0f);
}

__device__ __forceinline__ float ref_safe_div(float num, float den) {
    float sgn  = (den > 0.0f) ? 1.0f : ((den < 0.0f) ? -1.0f : 0.0f);
    float safe = __fmul_rn(fmaxf(fabsf(den), EPS_F), sgn);
    return __fdiv_rn(num, safe);
}

__device__ __forceinline__ float edge_quad(float2 a, float2 b) {
    float aa  = ref_inner(a.x, a.y, a.x, a.y);
    float bb  = ref_inner(b.x, b.y, b.x, b.y);
    float ab  = ref_inner(a.x, a.y, b.x, b.y);
    float den = __fmul_rn(aa, bb);
    float num = __fsub_rn(__fmul_rn(ab, ab), den);
    return ref_safe_div(num, den);
}

// ---------------------------------------------------------------------------
// Kernel A: build compact (x,y) table + per-block compactness partials.
__global__ __launch_bounds__(NTHR)
void node_kernel(const float* __restrict__ z, int n_nodes) {
    __shared__ double s_red[32];
    int i = blockIdx.x * NTHR + threadIdx.x;
    double comp = 0.0;
    if (i < n_nodes) {
        float2 xy = *reinterpret_cast<const float2*>(z + (size_t)i * DIM);
        g_tab[i] = xy;
        float aa  = ref_inner(xy.x, xy.y, xy.x, xy.y);
        float num = __fsub_rn(1.0f, aa);   // ab*ab - aa*bb with ab=bb=1
        comp = (double)ref_safe_div(num, aa);
    }
    double bsum = block_reduce_double(comp, s_red);
    if (threadIdx.x == 0) g_part_comp[blockIdx.x] = bsum;
}

// ---------------------------------------------------------------------------
// Kernel B: proximity over edges, gathers via ld.global.cg (L2-only).
__global__ __launch_bounds__(NTHR)
void edge_kernel(const int* __restrict__ src,
                 const int* __restrict__ dst,
                 long long n_edges, int n_nodes, int n_comp_blocks,
                 float* __restrict__ out) {
    __shared__ double s_red[32];
    __shared__ double s_pc[2];
    __shared__ unsigned int s_last;

    long long tid    = (long long)blockIdx.x * NTHR + threadIdx.x;
    long long stride = (long long)gridDim.x * NTHR;

    double prox = 0.0;
    long long n4 = n_edges >> 2;
    const int4* s4 = reinterpret_cast<const int4*>(src);
    const int4* d4 = reinterpret_cast<const int4*>(dst);
    #pragma unroll 1
    for (long long i = tid; i < n4; i += stride) {
        int4 s = __ldcs(s4 + i);
        int4 d = __ldcs(d4 + i);
        float2 a0 = ldcg_f2(&g_tab[s.x]), b0 = ldcg_f2(&g_tab[d.x]);
        float2 a1 = ldcg_f2(&g_tab[s.y]), b1 = ldcg_f2(&g_tab[d.y]);
        float2 a2 = ldcg_f2(&g_tab[s.z]), b2 = ldcg_f2(&g_tab[d.z]);
        float2 a3 = ldcg_f2(&g_tab[s.w]), b3 = ldcg_f2(&g_tab[d.w]);
        float q0 = edge_quad(a0, b0);
        float q1 = edge_quad(a1, b1);
        float q2 = edge_quad(a2, b2);
        float q3 = edge_quad(a3, b3);
        prox += (double)__fadd_rn(__fadd_rn(q0, q1), __fadd_rn(q2, q3));
    }
    for (long long e = (n4 << 2) + tid; e < n_edges; e += stride) {
        prox += (double)edge_quad(ldcg_f2(&g_tab[src[e]]), ldcg_f2(&g_tab[dst[e]]));
    }

    double bp = block_reduce_double(prox, s_red);
    if (threadIdx.x == 0) {
        g_part_prox[blockIdx.x] = bp;
        __threadfence();
        unsigned int t = atomicAdd(&g_done, 1u);
        s_last = (t == gridDim.x - 1) ? 1u : 0u;
    }
    __syncthreads();

    if (s_last) {
        double p = 0.0, c = 0.0;
        for (int i = threadIdx.x; i < gridDim.x; i += NTHR) p += g_part_prox[i];
        for (int i = threadIdx.x; i < n_comp_blocks; i += NTHR) c += g_part_comp[i];
        p = block_reduce_double(p, s_red);
        __syncthreads();
        c = block_reduce_double(c, s_red);
        if (threadIdx.x == 0) { s_pc[0] = p; s_pc[1] = c; }
        __syncthreads();

        if (threadIdx.x < 32) {
            int n_sp = (int)((n_edges < 10) ? n_edges : 10);
            double q = 0.0;
            if (threadIdx.x < n_sp) {
                float2 a = g_tab[src[threadIdx.x]];
                float2 b = g_tab[dst[threadIdx.x]];
                // lines: cross([x,y,1],[0,0,1]) = (y, -x, 0); time = 0
                float aa  = -__fadd_rn(__fmul_rn(a.y, a.y), __fmul_rn(a.x, a.x));
                float bb  = -__fadd_rn(__fmul_rn(b.y, b.y), __fmul_rn(b.x, b.x));
                float ab  = -__fadd_rn(__fmul_rn(a.y, b.y), __fmul_rn(a.x, b.x));
                float den = __fmul_rn(aa, bb);
                float num = __fsub_rn(__fmul_rn(ab, ab), den);
                q = (double)ref_safe_div(num, den);
            }
            #pragma unroll
            for (int o = 16; o; o >>= 1) q += __shfl_down_sync(0xffffffffu, q, o);
            if (threadIdx.x == 0) {
                double prox_m = s_pc[0] / (double)n_edges;
                double comp_m = s_pc[1] / (double)n_nodes;
                double spr_m  = q / (double)n_sp;
                out[0] = (float)((prox_m + comp_m) + 0.1 * spr_m);
                g_done = 0u;   // reset for next graph replay
            }
        }
    }
}

// ---------------------------------------------------------------------------
extern "C" void kernel_launch(void* const* d_in, const int* in_sizes, int n_in,
                              void* d_out, int out_size) {
    const float* z  = (const float*)d_in[0];
    const int*   ei = (const int*)d_in[1];

    int       n_nodes = in_sizes[0] / DIM;
    long long n_edges = (long long)in_sizes[1] / 2;
    const int* src = ei;
    const int* dst = ei + n_edges;

    int nba = (n_nodes + NTHR - 1) / NTHR;
    node_kernel<<<nba, NTHR>>>(z, n_nodes);
    edge_kernel<<<EBLK, NTHR>>>(src, dst, n_edges, n_nodes, nba, (float*)d_out);
}

// round 9
// speedup vs baseline: 5.6146x; 1.0451x over previous
#include <cuda_runtime.h>
#include <cstdint>

#define EPS_F 1e-9f
#define DIM   128
#define NTHR  256
#define EBLK  1184
#define NBA_MAX 1024
#define MAX_NODES 200000

// Scratch (no allocations allowed)
__device__ float2       g_tab[MAX_NODES];
__device__ double       g_part_prox[EBLK];
__device__ double       g_part_comp[NBA_MAX];
__device__ unsigned int g_done = 0;

// ---------------------------------------------------------------------------
__device__ __forceinline__ double block_reduce_double(double v, double* s) {
    int lane = threadIdx.x & 31;
    int wid  = threadIdx.x >> 5;
    #pragma unroll
    for (int o = 16; o; o >>= 1) v += __shfl_down_sync(0xffffffffu, v, o);
    if (lane == 0) s[wid] = v;
    __syncthreads();
    v = (threadIdx.x < (NTHR >> 5)) ? s[threadIdx.x] : 0.0;
    if (wid == 0) {
        #pragma unroll
        for (int o = 16; o; o >>= 1) v += __shfl_down_sync(0xffffffffu, v, o);
    }
    return v;  // valid on thread 0
}

// Exact fp32 rounding-order replication of the reference (no FMA contraction).
__device__ __forceinline__ float ref_inner(float ax, float ay, float bx, float by) {
    float u = __fadd_rn(__fmul_rn(ax, bx), __fmul_rn(ay, by));
    return __fadd_rn(-u, 1.0f);
}

__device__ __forceinline__ float ref_safe_div(float num, float den) {
    float sgn  = (den > 0.0f) ? 1.0f : ((den < 0.0f) ? -1.0f : 0.0f);
    float safe = __fmul_rn(fmaxf(fabsf(den), EPS_F), sgn);
    return __fdiv_rn(num, safe);
}

__device__ __forceinline__ float edge_quad(float2 a, float2 b) {
    float aa  = ref_inner(a.x, a.y, a.x, a.y);
    float bb  = ref_inner(b.x, b.y, b.x, b.y);
    float ab  = ref_inner(a.x, a.y, b.x, b.y);
    float den = __fmul_rn(aa, bb);
    float num = __fsub_rn(__fmul_rn(ab, ab), den);
    return ref_safe_div(num, den);
}

// ---------------------------------------------------------------------------
// Kernel A: build compact (x,y) table + per-block compactness partials.
__global__ __launch_bounds__(NTHR)
void node_kernel(const float* __restrict__ z, int n_nodes) {
    __shared__ double s_red[32];
    int i = blockIdx.x * NTHR + threadIdx.x;
    double comp = 0.0;
    if (i < n_nodes) {
        float2 xy = *reinterpret_cast<const float2*>(z + (size_t)i * DIM);
        g_tab[i] = xy;
        float aa  = ref_inner(xy.x, xy.y, xy.x, xy.y);
        float num = __fsub_rn(1.0f, aa);   // ab*ab - aa*bb with ab=bb=1
        comp = (double)ref_safe_div(num, aa);
    }
    double bsum = block_reduce_double(comp, s_red);
    if (threadIdx.x == 0) g_part_comp[blockIdx.x] = bsum;
}

// ---------------------------------------------------------------------------
// Kernel B: proximity over edges (R3 config). Launched with PDL so its setup
// and first index prefetch overlap node_kernel's tail.
__global__ __launch_bounds__(NTHR)
void edge_kernel(const int* __restrict__ src,
                 const int* __restrict__ dst,
                 long long n_edges, int n_nodes, int n_comp_blocks,
                 float* __restrict__ out) {
    __shared__ double s_red[32];
    __shared__ double s_pc[2];
    __shared__ unsigned int s_last;

    long long tid    = (long long)blockIdx.x * NTHR + threadIdx.x;
    long long stride = (long long)gridDim.x * NTHR;

    long long n4 = n_edges >> 2;
    const int4* s4 = reinterpret_cast<const int4*>(src);
    const int4* d4 = reinterpret_cast<const int4*>(dst);

    // Prefetch this thread's first indices while the node kernel drains.
    int4 s_pre = make_int4(0, 0, 0, 0), d_pre = make_int4(0, 0, 0, 0);
    bool has_pre = (tid < n4);
    if (has_pre) {
        s_pre = __ldcs(s4 + tid);
        d_pre = __ldcs(d4 + tid);
    }

    // Wait for node_kernel completion (table writes flushed & visible).
    cudaGridDependencySynchronize();

    double prox = 0.0;
    for (long long i = tid; i < n4; i += stride) {
        int4 s, d;
        if (i == tid && has_pre) { s = s_pre; d = d_pre; }
        else { s = __ldcs(s4 + i); d = __ldcs(d4 + i); }
        float2 a0 = g_tab[s.x], b0 = g_tab[d.x];
        float2 a1 = g_tab[s.y], b1 = g_tab[d.y];
        float2 a2 = g_tab[s.z], b2 = g_tab[d.z];
        float2 a3 = g_tab[s.w], b3 = g_tab[d.w];
        float q0 = edge_quad(a0, b0);
        float q1 = edge_quad(a1, b1);
        float q2 = edge_quad(a2, b2);
        float q3 = edge_quad(a3, b3);
        prox += (double)__fadd_rn(__fadd_rn(q0, q1), __fadd_rn(q2, q3));
    }
    for (long long e = (n4 << 2) + tid; e < n_edges; e += stride) {
        prox += (double)edge_quad(g_tab[src[e]], g_tab[dst[e]]);
    }

    double bp = block_reduce_double(prox, s_red);
    if (threadIdx.x == 0) {
        g_part_prox[blockIdx.x] = bp;
        __threadfence();
        unsigned int t = atomicAdd(&g_done, 1u);
        s_last = (t == gridDim.x - 1) ? 1u : 0u;
    }
    __syncthreads();

    if (s_last) {
        double p = 0.0, c = 0.0;
        for (int i = threadIdx.x; i < gridDim.x; i += NTHR) p += g_part_prox[i];
        for (int i = threadIdx.x; i < n_comp_blocks; i += NTHR) c += g_part_comp[i];
        p = block_reduce_double(p, s_red);
        __syncthreads();
        c = block_reduce_double(c, s_red);
        if (threadIdx.x == 0) { s_pc[0] = p; s_pc[1] = c; }
        __syncthreads();

        if (threadIdx.x < 32) {
            int n_sp = (int)((n_edges < 10) ? n_edges : 10);
            double q = 0.0;
            if (threadIdx.x < n_sp) {
                float2 a = g_tab[src[threadIdx.x]];
                float2 b = g_tab[dst[threadIdx.x]];
                // lines: cross([x,y,1],[0,0,1]) = (y, -x, 0); time = 0
                float aa  = -__fadd_rn(__fmul_rn(a.y, a.y), __fmul_rn(a.x, a.x));
                float bb  = -__fadd_rn(__fmul_rn(b.y, b.y), __fmul_rn(b.x, b.x));
                float ab  = -__fadd_rn(__fmul_rn(a.y, b.y), __fmul_rn(a.x, b.x));
                float den = __fmul_rn(aa, bb);
                float num = __fsub_rn(__fmul_rn(ab, ab), den);
                q = (double)ref_safe_div(num, den);
            }
            #pragma unroll
            for (int o = 16; o; o >>= 1) q += __shfl_down_sync(0xffffffffu, q, o);
            if (threadIdx.x == 0) {
                double prox_m = s_pc[0] / (double)n_edges;
                double comp_m = s_pc[1] / (double)n_nodes;
                double spr_m  = q / (double)n_sp;
                out[0] = (float)((prox_m + comp_m) + 0.1 * spr_m);
                g_done = 0u;   // reset for next graph replay
            }
        }
    }
}

// ---------------------------------------------------------------------------
extern "C" void kernel_launch(void* const* d_in, const int* in_sizes, int n_in,
                              void* d_out, int out_size) {
    const float* z  = (const float*)d_in[0];
    const int*   ei = (const int*)d_in[1];

    int       n_nodes = in_sizes[0] / DIM;
    long long n_edges = (long long)in_sizes[1] / 2;
    const int* src = ei;
    const int* dst = ei + n_edges;

    int nba = (n_nodes + NTHR - 1) / NTHR;
    node_kernel<<<nba, NTHR>>>(z, n_nodes);

    // Edge kernel with programmatic dependent launch: overlaps its setup with
    // node_kernel's tail; cudaGridDependencySynchronize() inside the kernel
    // enforces the table dependency.
    cudaLaunchConfig_t cfg = {};
    cfg.gridDim  = dim3(EBLK, 1, 1);
    cfg.blockDim = dim3(NTHR, 1, 1);
    cfg.dynamicSmemBytes = 0;
    cfg.stream = 0;
    cudaLaunchAttribute attr[1];
    attr[0].id = cudaLaunchAttributeProgrammaticStreamSerialization;
    attr[0].val.programmaticStreamSerializationAllowed = 1;
    cfg.attrs = attr;
    cfg.numAttrs = 1;
    cudaLaunchKernelEx(&cfg, edge_kernel, src, dst, n_edges, n_nodes, nba,
                       (float*)d_out);
}